// round 17
// baseline (speedup 1.0000x reference)
#include <cuda_runtime.h>
#include <math.h>

// Hausdorff, D=H=W=20, V=8000, batch 2. Exact integer squared-EDT.
// ONE kernel, 80 blocks: block = (transform t, z-plane z0).
// Thread map: warp = x (20 warps), lane = y (lanes 20-31 idle). y-pass is
// done IN-WARP via shuffles (no F1 smem, one less sync). x-pass via F2 smem.
// Front: strided float4 row loads + O(1) clz/ffs z-pass. Tail (R16): plain
// warp-max stores + tid0 scan -> one relaxed atomicMax + acq_rel arrival;
// last block decodes and resets (graph-replay safe).
// Encoding (monotone): 1..1083 -> sqrt/20 ; 2000 -> 999 ; 3000 -> 1e9 ; 0 none.

#define INF_S 32000   // max legit squared distance = 3*19^2 = 1083
#define PAD   8

__device__ unsigned g_slot[2 * PAD];   // per-sample encoded haus max; zero-init
__device__ unsigned g_done = 0;

__device__ __forceinline__ unsigned atom_add_acq_rel(unsigned* p, unsigned v)
{
    unsigned old;
    asm volatile("atom.acq_rel.gpu.global.add.u32 %0, [%1], %2;"
                 : "=r"(old) : "l"(p), "r"(v) : "memory");
    return old;
}

__global__ void __launch_bounds__(640, 1)
haus_plane(const float* __restrict__ predict,
           const float* __restrict__ targetp,
           float* __restrict__ out)
{
    __shared__ int F2[400];            // y-pass result, index x*20+y
    __shared__ int wmax[20];           // per-warp enc maxima (plain stores)
    __shared__ int sany;

    const int b  = blockIdx.x;         // t*20 + z0
    const int t  = b / 20, z0 = b - t * 20;
    const int n  = t >> 1,  m  = t & 1;
    const float* setSrc = (m ? targetp : predict) + n * 8000;
    const float* othSrc = (m ? predict : targetp) + n * 8000;
    const int tid  = threadIdx.x;
    const int lane = tid & 31;
    const int x    = tid >> 5;         // warp id 0..19
    const int y    = lane;             // valid when lane < 20
    const bool act = (lane < 20);

    if (tid == 0) sany = 0;

    // ---- front: own (x,y) row over z (5 x float4, MLP=5) + O(1) z-pass ----
    int F1val = INF_S;
    int oo = 0;
    unsigned rowbits = 0;
    if (act) {
        const int row = x * 20 + y;
        const float4* rp = (const float4*)(setSrc + row * 20);
        float ov = othSrc[row * 20 + z0];          // other mask at own cell
        #pragma unroll
        for (int q = 0; q < 5; q++) {
            float4 v = rp[q];
            // jnp.round == round-half-even == rintf
            rowbits |= (rintf(v.x) != 0.0f ? 1u : 0u) << (q * 4 + 0);
            rowbits |= (rintf(v.y) != 0.0f ? 1u : 0u) << (q * 4 + 1);
            rowbits |= (rintf(v.z) != 0.0f ? 1u : 0u) << (q * 4 + 2);
            rowbits |= (rintf(v.w) != 0.0f ? 1u : 0u) << (q * 4 + 3);
        }
        int dist = 100;
        unsigned lo = rowbits & ((2u << z0) - 1u);
        if (lo) dist = z0 - (31 - __clz(lo));
        unsigned hi = rowbits >> z0;
        if (hi) dist = min(dist, __ffs(hi) - 1);
        F1val = (dist <= 19) ? dist * dist : INF_S;

        int s = (rowbits >> z0) & 1;
        oo = (rintf(ov) != 0.0f) & (s ^ 1);        // "other-only" point
    }
    // anyS: 400 active rows cover the whole set volume
    int anyW = __any_sync(0xffffffffu, rowbits != 0);
    if (lane == 0 && anyW) sany = 1;               // benign race

    // ---- y-pass IN-WARP: F2(x,y) = min_yp F1(x,yp) + (y-yp)^2 ----
    {
        int c[20];
        #pragma unroll
        for (int yp = 0; yp < 20; yp++) {
            int f = __shfl_sync(0xffffffffu, F1val, yp);
            int dy = y - yp;
            c[yp] = f + dy * dy;
        }
        #pragma unroll
        for (int st = 1; st < 20; st <<= 1)
            #pragma unroll
            for (int i = 0; i + st < 20; i += (st << 1)) c[i] = min(c[i], c[i + st]);
        if (act) F2[x * 20 + y] = min(c[0], INF_S);
    }
    __syncthreads();

    // ---- x-pass + classification ----
    int enc = 0;                                   // d2 of other-only point; 0 = none
    if (act) {
        int c[20];
        #pragma unroll
        for (int xp = 0; xp < 20; xp++) {
            int dx = x - xp;
            c[xp] = F2[xp * 20 + y] + dx * dx;
        }
        #pragma unroll
        for (int st = 1; st < 20; st <<= 1)
            #pragma unroll
            for (int i = 0; i + st < 20; i += (st << 1)) c[i] = min(c[i], c[i + st]);
        if (oo) enc = c[0];                        // >= 1 (cell not in set)
    }
    enc = __reduce_max_sync(0xffffffffu, enc);
    if (lane == 0) wmax[x] = enc;                  // plain store, no atomics
    __syncthreads();

    // ---- tail: tid0 scans 20 warp maxima, ONE relaxed atomicMax + arrival ----
    if (tid == 0) {
        int red = 0;
        #pragma unroll
        for (int w = 0; w < 20; w++) red = max(red, wmax[w]);
        if (red) {
            unsigned e = sany ? (unsigned)red : (m ? 3000u : 2000u);
            atomicMax(&g_slot[n * PAD], e);
        }
        unsigned done = atom_add_acq_rel(&g_done, 1);   // release publishes the max
        if (done == 79) {                               // acquire: sees all slots
            float sum = 0.0f;
            #pragma unroll
            for (int nn = 0; nn < 2; nn++) {
                unsigned ev = *(volatile unsigned*)&g_slot[nn * PAD];
                float h = 0.0f;
                if (ev) h = (ev >= 3000u) ? 1e9f
                          : (ev >= 2000u) ? 999.0f
                          : sqrtf((float)ev) * 0.05f;
                sum += h;
                *(volatile unsigned*)&g_slot[nn * PAD] = 0;
            }
            out[0] = sum * 0.5f;
            *(volatile unsigned*)&g_done = 0;           // restore static-init state
        }
    }
}

extern "C" void kernel_launch(void* const* d_in, const int* in_sizes, int n_in,
                              void* d_out, int out_size)
{
    const float* predict = (const float*)d_in[0];
    const float* targetp = (const float*)d_in[1];
    haus_plane<<<80, 640>>>(predict, targetp, (float*)d_out);
}